// round 2
// baseline (speedup 1.0000x reference)
#include <cuda_runtime.h>

#define NUM_E 64
#define DIM_IN 512
#define DIM_OUT 512
#define CAP 3072

#define BM 128
#define BN 128
#define BK 16
#define TM 8
#define TN 8
// 256 threads: 16x16 thread grid, each computes TM x TN = 8x8

__device__ int g_off[NUM_E];

__global__ void scan_kernel(const int* __restrict__ sizes) {
    __shared__ int s[NUM_E];
    int t = threadIdx.x;
    s[t] = sizes[t];
    __syncthreads();
    if (t == 0) {
        int acc = 0;
        #pragma unroll
        for (int i = 0; i < NUM_E; i++) { int v = s[i]; s[i] = acc; acc += v; }
    }
    __syncthreads();
    g_off[t] = s[t];
}

__global__ __launch_bounds__(256, 2)
void grouped_gemm(const float* __restrict__ inputs,
                  const int*   __restrict__ sizes,
                  const float* __restrict__ weight,
                  float*       __restrict__ out) {
    const int e    = blockIdx.z;
    const int size = sizes[e];
    const int row0 = blockIdx.x * BM;
    if (row0 >= size) return;                 // empty tile for this expert
    const int base = g_off[e];
    const int col0 = blockIdx.y * BN;

    __shared__ float As[BK][BM];              // transposed A tile
    __shared__ float Bs[BK][BN];

    const int tid = threadIdx.x;
    const int tx  = tid & 15;                 // col group (0..15)
    const int ty  = tid >> 4;                 // row group (0..15)

    const float* A = inputs + (long)(base + row0) * DIM_IN;
    const float* B = weight + (long)e * DIM_IN * DIM_OUT + col0;
    float*       C = out    + (long)(base + row0) * DIM_OUT + col0;

    // A tile: BM x BK = 128x16 floats = 512 float4. Each thread: 2 float4.
    const int a_r0 = tid >> 2;                // 0..63
    const int a_c0 = (tid & 3) * 4;           // 0,4,8,12
    const int a_r1 = a_r0 + 64;
    // B tile: BK x BN = 16x128 floats = 512 float4. Each thread: 2 float4.
    const int b_r0 = tid >> 5;                // 0..7
    const int b_c0 = (tid & 31) * 4;          // 0..124
    const int b_r1 = b_r0 + 8;

    const bool a_v0 = (row0 + a_r0) < size;
    const bool a_v1 = (row0 + a_r1) < size;

    float4 ra0, ra1, rb0, rb1;

    // ---- prologue: load k-tile 0 ----
    {
        ra0 = a_v0 ? *(const float4*)(A + (long)a_r0 * DIM_IN + a_c0) : make_float4(0.f,0.f,0.f,0.f);
        ra1 = a_v1 ? *(const float4*)(A + (long)a_r1 * DIM_IN + a_c0) : make_float4(0.f,0.f,0.f,0.f);
        rb0 = *(const float4*)(B + (long)(b_r0) * DIM_OUT + b_c0);
        rb1 = *(const float4*)(B + (long)(b_r1) * DIM_OUT + b_c0);
    }
    // store to smem (A transposed)
    As[a_c0+0][a_r0] = ra0.x; As[a_c0+1][a_r0] = ra0.y; As[a_c0+2][a_r0] = ra0.z; As[a_c0+3][a_r0] = ra0.w;
    As[a_c0+0][a_r1] = ra1.x; As[a_c0+1][a_r1] = ra1.y; As[a_c0+2][a_r1] = ra1.z; As[a_c0+3][a_r1] = ra1.w;
    *(float4*)&Bs[b_r0][b_c0] = rb0;
    *(float4*)&Bs[b_r1][b_c0] = rb1;
    __syncthreads();

    float acc[TM][TN];
    #pragma unroll
    for (int i = 0; i < TM; i++)
        #pragma unroll
        for (int j = 0; j < TN; j++) acc[i][j] = 0.f;

    const int mrow = ty * TM;
    const int ncol = tx * TN;

    for (int k0 = BK; k0 <= DIM_IN; k0 += BK) {
        // prefetch next k-tile into registers (skipped on last iter)
        if (k0 < DIM_IN) {
            ra0 = a_v0 ? *(const float4*)(A + (long)a_r0 * DIM_IN + k0 + a_c0) : make_float4(0.f,0.f,0.f,0.f);
            ra1 = a_v1 ? *(const float4*)(A + (long)a_r1 * DIM_IN + k0 + a_c0) : make_float4(0.f,0.f,0.f,0.f);
            rb0 = *(const float4*)(B + (long)(k0 + b_r0) * DIM_OUT + b_c0);
            rb1 = *(const float4*)(B + (long)(k0 + b_r1) * DIM_OUT + b_c0);
        }

        // compute current tile
        #pragma unroll
        for (int k = 0; k < BK; k++) {
            float av[TM], bv[TN];
            #pragma unroll
            for (int i = 0; i < TM; i += 4)
                *(float4*)&av[i] = *(const float4*)&As[k][mrow + i];
            #pragma unroll
            for (int j = 0; j < TN; j += 4)
                *(float4*)&bv[j] = *(const float4*)&Bs[k][ncol + j];
            #pragma unroll
            for (int i = 0; i < TM; i++)
                #pragma unroll
                for (int j = 0; j < TN; j++)
                    acc[i][j] = fmaf(av[i], bv[j], acc[i][j]);
        }

        if (k0 < DIM_IN) {
            __syncthreads();
            As[a_c0+0][a_r0] = ra0.x; As[a_c0+1][a_r0] = ra0.y; As[a_c0+2][a_r0] = ra0.z; As[a_c0+3][a_r0] = ra0.w;
            As[a_c0+0][a_r1] = ra1.x; As[a_c0+1][a_r1] = ra1.y; As[a_c0+2][a_r1] = ra1.z; As[a_c0+3][a_r1] = ra1.w;
            *(float4*)&Bs[b_r0][b_c0] = rb0;
            *(float4*)&Bs[b_r1][b_c0] = rb1;
            __syncthreads();
        }
    }

    // ---- epilogue: guarded vectorized store ----
    #pragma unroll
    for (int i = 0; i < TM; i++) {
        int r = mrow + i;
        if (row0 + r < size) {
            float* cp = C + (long)r * DIM_OUT + ncol;
            *(float4*)(cp + 0) = make_float4(acc[i][0], acc[i][1], acc[i][2], acc[i][3]);
            *(float4*)(cp + 4) = make_float4(acc[i][4], acc[i][5], acc[i][6], acc[i][7]);
        }
    }
}

extern "C" void kernel_launch(void* const* d_in, const int* in_sizes, int n_in,
                              void* d_out, int out_size) {
    const float* inputs = (const float*)d_in[0];
    const int*   sizes  = (const int*)  d_in[1];
    const float* weight = (const float*)d_in[2];
    float*       out    = (float*)d_out;

    scan_kernel<<<1, NUM_E>>>(sizes);

    dim3 grid(CAP / BM, DIM_OUT / BN, NUM_E);   // (24, 4, 64)
    grouped_gemm<<<grid, 256>>>(inputs, sizes, weight, out);
}

// round 5
// speedup vs baseline: 2.0371x; 2.0371x over previous
#include <cuda_runtime.h>
#include <cuda_bf16.h>
#include <cstdint>

#define NUM_E 64
#define DIM 512
#define NTOK 131072
#define CAP 3072

#define BM 128
#define BN 128
#define BK 32
#define NCHUNK 16            // 512 / 32
#define NSTAGE 3

#define A_STRIDE 80          // bytes per A smem row (64B data + pad)
#define B_STRIDE 272         // bytes per B smem row (256B data + pad)
#define A_TILE_BYTES (BM * A_STRIDE)          // 10240
#define B_TILE_BYTES (BK * B_STRIDE)          // 8704
#define STAGE_BYTES (2 * A_TILE_BYTES + 2 * B_TILE_BYTES)  // 37888
#define SMEM_TOTAL (NSTAGE * STAGE_BYTES)     // 113664

// ---------------- scratch ----------------
__device__ int g_off[NUM_E];
__device__ unsigned short g_a_hi[(size_t)NTOK * DIM];
__device__ unsigned short g_a_lo[(size_t)NTOK * DIM];
__device__ unsigned short g_w_hi[(size_t)NUM_E * DIM * DIM];
__device__ unsigned short g_w_lo[(size_t)NUM_E * DIM * DIM];

// ---------------- helpers ----------------
__device__ __forceinline__ uint32_t smem_u32(const void* p) {
    uint32_t a;
    asm("{ .reg .u64 t; cvta.to.shared.u64 t, %1; cvt.u32.u64 %0, t; }" : "=r"(a) : "l"(p));
    return a;
}

__device__ __forceinline__ void cp16(uint32_t dst, const void* src, bool pred) {
    int sz = pred ? 16 : 0;
    asm volatile("cp.async.cg.shared.global [%0], [%1], 16, %2;"
        :: "r"(dst), "l"(src), "r"(sz) : "memory");
}

__device__ __forceinline__ void ldsm_x4(uint32_t* r, uint32_t addr) {
    asm volatile("ldmatrix.sync.aligned.m8n8.x4.shared.b16 {%0,%1,%2,%3}, [%4];"
        : "=r"(r[0]), "=r"(r[1]), "=r"(r[2]), "=r"(r[3]) : "r"(addr));
}
__device__ __forceinline__ void ldsm_x4_t(uint32_t* r, uint32_t addr) {
    asm volatile("ldmatrix.sync.aligned.m8n8.x4.trans.shared.b16 {%0,%1,%2,%3}, [%4];"
        : "=r"(r[0]), "=r"(r[1]), "=r"(r[2]), "=r"(r[3]) : "r"(addr));
}

__device__ __forceinline__ void mma16816(float* c, const uint32_t* a, const uint32_t* b) {
    asm volatile(
        "mma.sync.aligned.m16n8k16.row.col.f32.bf16.bf16.f32 "
        "{%0,%1,%2,%3}, {%4,%5,%6,%7}, {%8,%9}, {%0,%1,%2,%3};"
        : "+f"(c[0]), "+f"(c[1]), "+f"(c[2]), "+f"(c[3])
        : "r"(a[0]), "r"(a[1]), "r"(a[2]), "r"(a[3]), "r"(b[0]), "r"(b[1]));
}

// ---------------- small kernels ----------------
__global__ void scan_kernel(const int* __restrict__ sizes) {
    __shared__ int s[NUM_E];
    int t = threadIdx.x;
    s[t] = sizes[t];
    __syncthreads();
    if (t == 0) {
        int acc = 0;
        #pragma unroll
        for (int i = 0; i < NUM_E; i++) { int v = s[i]; s[i] = acc; acc += v; }
    }
    __syncthreads();
    g_off[t] = s[t];
}

__device__ __forceinline__ void split4(float4 v, ushort4& hv, ushort4& lv) {
    __nv_bfloat16 h0 = __float2bfloat16(v.x);
    __nv_bfloat16 h1 = __float2bfloat16(v.y);
    __nv_bfloat16 h2 = __float2bfloat16(v.z);
    __nv_bfloat16 h3 = __float2bfloat16(v.w);
    __nv_bfloat16 l0 = __float2bfloat16(v.x - __bfloat162float(h0));
    __nv_bfloat16 l1 = __float2bfloat16(v.y - __bfloat162float(h1));
    __nv_bfloat16 l2 = __float2bfloat16(v.z - __bfloat162float(h2));
    __nv_bfloat16 l3 = __float2bfloat16(v.w - __bfloat162float(h3));
    hv = make_ushort4(__bfloat16_as_ushort(h0), __bfloat16_as_ushort(h1),
                      __bfloat16_as_ushort(h2), __bfloat16_as_ushort(h3));
    lv = make_ushort4(__bfloat16_as_ushort(l0), __bfloat16_as_ushort(l1),
                      __bfloat16_as_ushort(l2), __bfloat16_as_ushort(l3));
}

__global__ void convert_a(const float* __restrict__ x) {
    size_t i = (size_t)blockIdx.x * blockDim.x + threadIdx.x;
    size_t stride = (size_t)gridDim.x * blockDim.x;
    const size_t total = (size_t)NTOK * DIM / 4;
    for (; i < total; i += stride) {
        ushort4 hv, lv;
        split4(((const float4*)x)[i], hv, lv);
        ((ushort4*)g_a_hi)[i] = hv;
        ((ushort4*)g_a_lo)[i] = lv;
    }
}

__global__ void convert_w(const float* __restrict__ w) {
    size_t i = (size_t)blockIdx.x * blockDim.x + threadIdx.x;
    size_t stride = (size_t)gridDim.x * blockDim.x;
    const size_t total = (size_t)NUM_E * DIM * DIM / 4;
    for (; i < total; i += stride) {
        ushort4 hv, lv;
        split4(((const float4*)w)[i], hv, lv);
        ((ushort4*)g_w_hi)[i] = hv;
        ((ushort4*)g_w_lo)[i] = lv;
    }
}

// ---------------- grouped GEMM ----------------
__device__ __forceinline__ void load_stage(uint32_t smem_base, int stage, int c,
                                           long tok_base, int e, int col0, int tid) {
    const int kk = c * BK;
    const uint32_t base = smem_base + stage * STAGE_BYTES;
    const uint32_t sAh = base;
    const uint32_t sAl = base + A_TILE_BYTES;
    const uint32_t sBh = base + 2 * A_TILE_BYTES;
    const uint32_t sBl = sBh + B_TILE_BYTES;
    // A: 128 rows x 64B data (4 x 16B chunks), stride 80B
    #pragma unroll
    for (int i = tid; i < 512; i += 256) {
        int r = i >> 2, ch = i & 3;
        long tok = tok_base + r;
        bool v = tok < (long)NTOK;
        size_t g = v ? ((size_t)tok * DIM + kk + ch * 8) : 0;
        uint32_t d = (uint32_t)(r * A_STRIDE + ch * 16);
        cp16(sAh + d, g_a_hi + g, v);
        cp16(sAl + d, g_a_lo + g, v);
    }
    // B: 32 k-rows x 256B data (16 x 16B chunks), stride 272B
    #pragma unroll
    for (int i = tid; i < 512; i += 256) {
        int r = i >> 4, ch = i & 15;
        size_t g = (size_t)e * DIM * DIM + (size_t)(kk + r) * DIM + col0 + ch * 8;
        uint32_t d = (uint32_t)(r * B_STRIDE + ch * 16);
        cp16(sBh + d, g_w_hi + g, true);
        cp16(sBl + d, g_w_lo + g, true);
    }
    asm volatile("cp.async.commit_group;" ::: "memory");
}

__global__ __launch_bounds__(256, 1)
void grouped_gemm(const int* __restrict__ sizes, float* __restrict__ out) {
    extern __shared__ char smem[];
    const int e = blockIdx.z;
    const int size = sizes[e];
    const int row0 = blockIdx.x * BM;
    if (row0 >= size) return;
    const int col0 = blockIdx.y * BN;
    const long tok_base = (long)g_off[e] + row0;

    const uint32_t smem_base = smem_u32(smem);
    const int tid = threadIdx.x;
    const int wid = tid >> 5;
    const int lane = tid & 31;
    const int wm = wid & 3;       // 4 warps along M: 32 rows each
    const int wn = wid >> 2;      // 2 warps along N: 64 cols each
    const int quad = lane >> 3;
    const int lr = lane & 7;

    float acc[2][8][4];
    #pragma unroll
    for (int mt = 0; mt < 2; mt++)
        #pragma unroll
        for (int nt = 0; nt < 8; nt++)
            #pragma unroll
            for (int q = 0; q < 4; q++) acc[mt][nt][q] = 0.f;

    // prologue
    load_stage(smem_base, 0, 0, tok_base, e, col0, tid);
    load_stage(smem_base, 1, 1, tok_base, e, col0, tid);

    for (int c = 0; c < NCHUNK; c++) {
        if (c + 2 < NCHUNK)
            load_stage(smem_base, (c + 2) % NSTAGE, c + 2, tok_base, e, col0, tid);
        if (c + 2 < NCHUNK)      asm volatile("cp.async.wait_group 2;" ::: "memory");
        else if (c + 1 < NCHUNK) asm volatile("cp.async.wait_group 1;" ::: "memory");
        else                     asm volatile("cp.async.wait_group 0;" ::: "memory");
        __syncthreads();

        const uint32_t base = smem_base + (c % NSTAGE) * STAGE_BYTES;
        const uint32_t sAh = base;
        const uint32_t sAl = base + A_TILE_BYTES;
        const uint32_t sBh = base + 2 * A_TILE_BYTES;
        const uint32_t sBl = sBh + B_TILE_BYTES;

        #pragma unroll
        for (int s = 0; s < 2; s++) {
            uint32_t aHi[2][4], aLo[2][4], bHi[8][2], bLo[8][2];
            // A fragments: 16x16 (m x k) per ldmatrix.x4
            #pragma unroll
            for (int mt = 0; mt < 2; mt++) {
                int row = wm * 32 + mt * 16 + (quad & 1) * 8 + lr;
                int kb = s * 32 + (quad >> 1) * 16;
                uint32_t off = (uint32_t)(row * A_STRIDE + kb);
                ldsm_x4(aHi[mt], sAh + off);
                ldsm_x4(aLo[mt], sAl + off);
            }
            // B fragments: 16x16 (k x n) per ldmatrix.x4.trans
            #pragma unroll
            for (int nt2 = 0; nt2 < 4; nt2++) {
                int krow = s * 16 + (quad & 1) * 8 + lr;
                int nb = (wn * 64 + nt2 * 16 + (quad >> 1) * 8) * 2;
                uint32_t off = (uint32_t)(krow * B_STRIDE + nb);
                uint32_t rh[4], rl[4];
                ldsm_x4_t(rh, sBh + off);
                ldsm_x4_t(rl, sBl + off);
                bHi[2 * nt2][0] = rh[0]; bHi[2 * nt2][1] = rh[1];
                bHi[2 * nt2 + 1][0] = rh[2]; bHi[2 * nt2 + 1][1] = rh[3];
                bLo[2 * nt2][0] = rl[0]; bLo[2 * nt2][1] = rl[1];
                bLo[2 * nt2 + 1][0] = rl[2]; bLo[2 * nt2 + 1][1] = rl[3];
            }
            // 3-pass MMA
            #pragma unroll
            for (int mt = 0; mt < 2; mt++)
                #pragma unroll
                for (int nt = 0; nt < 8; nt++) {
                    mma16816(acc[mt][nt], aHi[mt], bHi[nt]);
                    mma16816(acc[mt][nt], aLo[mt], bHi[nt]);
                    mma16816(acc[mt][nt], aHi[mt], bLo[nt]);
                }
        }
        __syncthreads();
    }

    // ---- epilogue ----
    const int g = lane >> 2;
    const int q = lane & 3;
    #pragma unroll
    for (int mt = 0; mt < 2; mt++) {
        int r_lo = wm * 32 + mt * 16 + g;       // tile-local rows
        int r_hi = r_lo + 8;
        bool v_lo = (row0 + r_lo) < size;
        bool v_hi = (row0 + r_hi) < size;
        float* p_lo = out + (size_t)(tok_base + r_lo) * DIM + col0;
        float* p_hi = out + (size_t)(tok_base + r_hi) * DIM + col0;
        #pragma unroll
        for (int nt = 0; nt < 8; nt++) {
            int cidx = wn * 64 + nt * 8 + q * 2;
            if (v_lo) *(float2*)(p_lo + cidx) = make_float2(acc[mt][nt][0], acc[mt][nt][1]);
            if (v_hi) *(float2*)(p_hi + cidx) = make_float2(acc[mt][nt][2], acc[mt][nt][3]);
        }
    }
}

// ---------------- launch ----------------
extern "C" void kernel_launch(void* const* d_in, const int* in_sizes, int n_in,
                              void* d_out, int out_size) {
    const float* inputs = (const float*)d_in[0];
    const int*   sizes  = (const int*)  d_in[1];
    const float* weight = (const float*)d_in[2];
    float*       out    = (float*)d_out;

    cudaFuncSetAttribute(grouped_gemm, cudaFuncAttributeMaxDynamicSharedMemorySize, SMEM_TOTAL);

    scan_kernel<<<1, NUM_E>>>(sizes);
    convert_a<<<2048, 256>>>(inputs);
    convert_w<<<2048, 256>>>(weight);
    grouped_gemm<<<dim3(CAP / BM, DIM / BN, NUM_E), 256, SMEM_TOTAL>>>(sizes, out);
}

// round 6
// speedup vs baseline: 2.4537x; 1.2045x over previous
#include <cuda_runtime.h>
#include <cuda_bf16.h>
#include <cstdint>

#define NUM_E 64
#define DIM 512
#define NTOK 131072
#define CAP 3072

#define BM 128
#define BN 128
#define BK 32
#define NCHUNK 16            // 512 / 32
#define NSTAGE 2

#define A_STRIDE 80          // bytes per A smem row (64B data + pad)
#define B_STRIDE 272         // bytes per B smem row (256B data + pad)
#define A_TILE_BYTES (BM * A_STRIDE)          // 10240
#define B_TILE_BYTES (BK * B_STRIDE)          // 8704
#define STAGE_BYTES (2 * A_TILE_BYTES + 2 * B_TILE_BYTES)  // 37888
#define SMEM_TOTAL (NSTAGE * STAGE_BYTES)     // 75776 -> 2 CTAs/SM

// ---------------- scratch ----------------
__device__ int g_off[NUM_E];
__device__ unsigned short g_a_hi[(size_t)NTOK * DIM];
__device__ unsigned short g_a_lo[(size_t)NTOK * DIM];
__device__ unsigned short g_w_hi[(size_t)NUM_E * DIM * DIM];
__device__ unsigned short g_w_lo[(size_t)NUM_E * DIM * DIM];

// ---------------- helpers ----------------
__device__ __forceinline__ uint32_t smem_u32(const void* p) {
    uint32_t a;
    asm("{ .reg .u64 t; cvta.to.shared.u64 t, %1; cvt.u32.u64 %0, t; }" : "=r"(a) : "l"(p));
    return a;
}

__device__ __forceinline__ void cp16(uint32_t dst, const void* src, bool pred) {
    int sz = pred ? 16 : 0;
    asm volatile("cp.async.cg.shared.global [%0], [%1], 16, %2;"
        :: "r"(dst), "l"(src), "r"(sz) : "memory");
}

__device__ __forceinline__ void ldsm_x4(uint32_t* r, uint32_t addr) {
    asm volatile("ldmatrix.sync.aligned.m8n8.x4.shared.b16 {%0,%1,%2,%3}, [%4];"
        : "=r"(r[0]), "=r"(r[1]), "=r"(r[2]), "=r"(r[3]) : "r"(addr));
}
__device__ __forceinline__ void ldsm_x4_t(uint32_t* r, uint32_t addr) {
    asm volatile("ldmatrix.sync.aligned.m8n8.x4.trans.shared.b16 {%0,%1,%2,%3}, [%4];"
        : "=r"(r[0]), "=r"(r[1]), "=r"(r[2]), "=r"(r[3]) : "r"(addr));
}

__device__ __forceinline__ void mma16816(float* c, const uint32_t* a, const uint32_t* b) {
    asm volatile(
        "mma.sync.aligned.m16n8k16.row.col.f32.bf16.bf16.f32 "
        "{%0,%1,%2,%3}, {%4,%5,%6,%7}, {%8,%9}, {%0,%1,%2,%3};"
        : "+f"(c[0]), "+f"(c[1]), "+f"(c[2]), "+f"(c[3])
        : "r"(a[0]), "r"(a[1]), "r"(a[2]), "r"(a[3]), "r"(b[0]), "r"(b[1]));
}

// ---------------- small kernels ----------------
__global__ void scan_kernel(const int* __restrict__ sizes) {
    __shared__ int s[NUM_E];
    int t = threadIdx.x;
    s[t] = sizes[t];
    __syncthreads();
    if (t == 0) {
        int acc = 0;
        #pragma unroll
        for (int i = 0; i < NUM_E; i++) { int v = s[i]; s[i] = acc; acc += v; }
    }
    __syncthreads();
    g_off[t] = s[t];
}

__device__ __forceinline__ void split4(float4 v, ushort4& hv, ushort4& lv) {
    __nv_bfloat16 h0 = __float2bfloat16(v.x);
    __nv_bfloat16 h1 = __float2bfloat16(v.y);
    __nv_bfloat16 h2 = __float2bfloat16(v.z);
    __nv_bfloat16 h3 = __float2bfloat16(v.w);
    __nv_bfloat16 l0 = __float2bfloat16(v.x - __bfloat162float(h0));
    __nv_bfloat16 l1 = __float2bfloat16(v.y - __bfloat162float(h1));
    __nv_bfloat16 l2 = __float2bfloat16(v.z - __bfloat162float(h2));
    __nv_bfloat16 l3 = __float2bfloat16(v.w - __bfloat162float(h3));
    hv = make_ushort4(__bfloat16_as_ushort(h0), __bfloat16_as_ushort(h1),
                      __bfloat16_as_ushort(h2), __bfloat16_as_ushort(h3));
    lv = make_ushort4(__bfloat16_as_ushort(l0), __bfloat16_as_ushort(l1),
                      __bfloat16_as_ushort(l2), __bfloat16_as_ushort(l3));
}

__global__ void convert_a(const float* __restrict__ x) {
    size_t i = (size_t)blockIdx.x * blockDim.x + threadIdx.x;
    size_t stride = (size_t)gridDim.x * blockDim.x;
    const size_t total = (size_t)NTOK * DIM / 4;
    for (; i < total; i += stride) {
        ushort4 hv, lv;
        split4(((const float4*)x)[i], hv, lv);
        ((ushort4*)g_a_hi)[i] = hv;
        ((ushort4*)g_a_lo)[i] = lv;
    }
}

__global__ void convert_w(const float* __restrict__ w) {
    size_t i = (size_t)blockIdx.x * blockDim.x + threadIdx.x;
    size_t stride = (size_t)gridDim.x * blockDim.x;
    const size_t total = (size_t)NUM_E * DIM * DIM / 4;
    for (; i < total; i += stride) {
        ushort4 hv, lv;
        split4(((const float4*)w)[i], hv, lv);
        ((ushort4*)g_w_hi)[i] = hv;
        ((ushort4*)g_w_lo)[i] = lv;
    }
}

// ---------------- grouped GEMM ----------------
__device__ __forceinline__ void load_stage(uint32_t smem_base, int stage, int c,
                                           long tok_base, int e, int col0, int tid) {
    const int kk = c * BK;
    const uint32_t base = smem_base + stage * STAGE_BYTES;
    const uint32_t sAh = base;
    const uint32_t sAl = base + A_TILE_BYTES;
    const uint32_t sBh = base + 2 * A_TILE_BYTES;
    const uint32_t sBl = sBh + B_TILE_BYTES;
    // A: 128 rows x 64B data (4 x 16B chunks), stride 80B
    #pragma unroll
    for (int i = tid; i < 512; i += 256) {
        int r = i >> 2, ch = i & 3;
        long tok = tok_base + r;
        bool v = tok < (long)NTOK;
        size_t g = v ? ((size_t)tok * DIM + kk + ch * 8) : 0;
        uint32_t d = (uint32_t)(r * A_STRIDE + ch * 16);
        cp16(sAh + d, g_a_hi + g, v);
        cp16(sAl + d, g_a_lo + g, v);
    }
    // B: 32 k-rows x 256B data (16 x 16B chunks), stride 272B
    #pragma unroll
    for (int i = tid; i < 512; i += 256) {
        int r = i >> 4, ch = i & 15;
        size_t g = (size_t)e * DIM * DIM + (size_t)(kk + r) * DIM + col0 + ch * 8;
        uint32_t d = (uint32_t)(r * B_STRIDE + ch * 16);
        cp16(sBh + d, g_w_hi + g, true);
        cp16(sBl + d, g_w_lo + g, true);
    }
    asm volatile("cp.async.commit_group;" ::: "memory");
}

__global__ __launch_bounds__(256, 2)
void grouped_gemm(const int* __restrict__ sizes, float* __restrict__ out) {
    extern __shared__ char smem[];
    const int e = blockIdx.z;
    const int size = sizes[e];
    const int row0 = blockIdx.x * BM;
    if (row0 >= size) return;
    const int col0 = blockIdx.y * BN;
    const long tok_base = (long)g_off[e] + row0;

    const uint32_t smem_base = smem_u32(smem);
    const int tid = threadIdx.x;
    const int wid = tid >> 5;
    const int lane = tid & 31;
    const int wm = wid & 3;       // 4 warps along M: 32 rows each
    const int wn = wid >> 2;      // 2 warps along N: 64 cols each
    const int quad = lane >> 3;
    const int lr = lane & 7;

    float acc[2][8][4];
    #pragma unroll
    for (int mt = 0; mt < 2; mt++)
        #pragma unroll
        for (int nt = 0; nt < 8; nt++)
            #pragma unroll
            for (int q = 0; q < 4; q++) acc[mt][nt][q] = 0.f;

    // prologue: depth-1 prefetch
    load_stage(smem_base, 0, 0, tok_base, e, col0, tid);

    for (int c = 0; c < NCHUNK; c++) {
        if (c > 0) __syncthreads();   // reads of stage (c+1)%2 (done in iter c-1) complete
        if (c + 1 < NCHUNK)
            load_stage(smem_base, (c + 1) & 1, c + 1, tok_base, e, col0, tid);
        if (c + 1 < NCHUNK) asm volatile("cp.async.wait_group 1;" ::: "memory");
        else                asm volatile("cp.async.wait_group 0;" ::: "memory");
        __syncthreads();              // chunk-c data visible to all warps

        const uint32_t base = smem_base + (c & 1) * STAGE_BYTES;
        const uint32_t sAh = base;
        const uint32_t sAl = base + A_TILE_BYTES;
        const uint32_t sBh = base + 2 * A_TILE_BYTES;
        const uint32_t sBl = sBh + B_TILE_BYTES;

        #pragma unroll
        for (int s = 0; s < 2; s++) {
            uint32_t aHi[2][4], aLo[2][4];
            // A fragments: 16x16 (m x k) per ldmatrix.x4
            #pragma unroll
            for (int mt = 0; mt < 2; mt++) {
                int row = wm * 32 + mt * 16 + (quad & 1) * 8 + lr;
                int kb = s * 32 + (quad >> 1) * 16;
                uint32_t off = (uint32_t)(row * A_STRIDE + kb);
                ldsm_x4(aHi[mt], sAh + off);
                ldsm_x4(aLo[mt], sAl + off);
            }
            // B fragments in two nt-halves to cap register pressure
            #pragma unroll
            for (int h = 0; h < 2; h++) {
                uint32_t bHi[4][2], bLo[4][2];
                #pragma unroll
                for (int j = 0; j < 2; j++) {
                    int nt2 = h * 2 + j;   // 16-col block index
                    int krow = s * 16 + (quad & 1) * 8 + lr;
                    int nb = (wn * 64 + nt2 * 16 + (quad >> 1) * 8) * 2;
                    uint32_t off = (uint32_t)(krow * B_STRIDE + nb);
                    uint32_t rh[4], rl[4];
                    ldsm_x4_t(rh, sBh + off);
                    ldsm_x4_t(rl, sBl + off);
                    bHi[2 * j][0] = rh[0]; bHi[2 * j][1] = rh[1];
                    bHi[2 * j + 1][0] = rh[2]; bHi[2 * j + 1][1] = rh[3];
                    bLo[2 * j][0] = rl[0]; bLo[2 * j][1] = rl[1];
                    bLo[2 * j + 1][0] = rl[2]; bLo[2 * j + 1][1] = rl[3];
                }
                #pragma unroll
                for (int mt = 0; mt < 2; mt++)
                    #pragma unroll
                    for (int j = 0; j < 4; j++) {
                        int nt = h * 4 + j;
                        mma16816(acc[mt][nt], aHi[mt], bHi[j]);
                        mma16816(acc[mt][nt], aLo[mt], bHi[j]);
                        mma16816(acc[mt][nt], aHi[mt], bLo[j]);
                    }
            }
        }
    }

    // ---- epilogue ----
    const int g = lane >> 2;
    const int q = lane & 3;
    #pragma unroll
    for (int mt = 0; mt < 2; mt++) {
        int r_lo = wm * 32 + mt * 16 + g;       // tile-local rows
        int r_hi = r_lo + 8;
        bool v_lo = (row0 + r_lo) < size;
        bool v_hi = (row0 + r_hi) < size;
        float* p_lo = out + (size_t)(tok_base + r_lo) * DIM + col0;
        float* p_hi = out + (size_t)(tok_base + r_hi) * DIM + col0;
        #pragma unroll
        for (int nt = 0; nt < 8; nt++) {
            int cidx = wn * 64 + nt * 8 + q * 2;
            if (v_lo) *(float2*)(p_lo + cidx) = make_float2(acc[mt][nt][0], acc[mt][nt][1]);
            if (v_hi) *(float2*)(p_hi + cidx) = make_float2(acc[mt][nt][2], acc[mt][nt][3]);
        }
    }
}

// ---------------- launch ----------------
extern "C" void kernel_launch(void* const* d_in, const int* in_sizes, int n_in,
                              void* d_out, int out_size) {
    const float* inputs = (const float*)d_in[0];
    const int*   sizes  = (const int*)  d_in[1];
    const float* weight = (const float*)d_in[2];
    float*       out    = (float*)d_out;

    cudaFuncSetAttribute(grouped_gemm, cudaFuncAttributeMaxDynamicSharedMemorySize, SMEM_TOTAL);

    scan_kernel<<<1, NUM_E>>>(sizes);
    convert_a<<<2048, 256>>>(inputs);
    convert_w<<<2048, 256>>>(weight);
    grouped_gemm<<<dim3(CAP / BM, DIM / BN, NUM_E), 256, SMEM_TOTAL>>>(sizes, out);
}

// round 8
// speedup vs baseline: 2.4583x; 1.0019x over previous
#include <cuda_runtime.h>
#include <cuda_bf16.h>
#include <cstdint>

#define NUM_E 64
#define DIM 512
#define NTOK 131072
#define CAP 3072

#define BM 128
#define BN 128
#define BK 32
#define NCHUNK 16            // 512 / 32
#define NSTAGE 3

#define A_STRIDE 80          // bytes per A smem row (64B data + pad)
#define B_STRIDE 272         // bytes per B smem row (256B data + pad)
#define A_TILE_BYTES (BM * A_STRIDE)          // 10240
#define B_TILE_BYTES (BK * B_STRIDE)          // 8704
#define STAGE_BYTES (2 * A_TILE_BYTES + 2 * B_TILE_BYTES)  // 37888
#define SMEM_TOTAL (NSTAGE * STAGE_BYTES)     // 113664; x2 CTAs = 227328 <= 228KB/SM

// ---------------- scratch ----------------
__device__ int g_off[NUM_E];
__device__ unsigned short g_a_hi[(size_t)NTOK * DIM];
__device__ unsigned short g_a_lo[(size_t)NTOK * DIM];
__device__ unsigned short g_w_hi[(size_t)NUM_E * DIM * DIM];
__device__ unsigned short g_w_lo[(size_t)NUM_E * DIM * DIM];

// ---------------- helpers ----------------
__device__ __forceinline__ uint32_t smem_u32(const void* p) {
    uint32_t a;
    asm("{ .reg .u64 t; cvta.to.shared.u64 t, %1; cvt.u32.u64 %0, t; }" : "=r"(a) : "l"(p));
    return a;
}

__device__ __forceinline__ void cp16(uint32_t dst, const void* src, bool pred) {
    int sz = pred ? 16 : 0;
    asm volatile("cp.async.cg.shared.global [%0], [%1], 16, %2;"
        :: "r"(dst), "l"(src), "r"(sz) : "memory");
}

__device__ __forceinline__ void ldsm_x4(uint32_t* r, uint32_t addr) {
    asm volatile("ldmatrix.sync.aligned.m8n8.x4.shared.b16 {%0,%1,%2,%3}, [%4];"
        : "=r"(r[0]), "=r"(r[1]), "=r"(r[2]), "=r"(r[3]) : "r"(addr));
}
__device__ __forceinline__ void ldsm_x4_t(uint32_t* r, uint32_t addr) {
    asm volatile("ldmatrix.sync.aligned.m8n8.x4.trans.shared.b16 {%0,%1,%2,%3}, [%4];"
        : "=r"(r[0]), "=r"(r[1]), "=r"(r[2]), "=r"(r[3]) : "r"(addr));
}

__device__ __forceinline__ void mma16816(float* c, const uint32_t* a, const uint32_t* b) {
    asm volatile(
        "mma.sync.aligned.m16n8k16.row.col.f32.bf16.bf16.f32 "
        "{%0,%1,%2,%3}, {%4,%5,%6,%7}, {%8,%9}, {%0,%1,%2,%3};"
        : "+f"(c[0]), "+f"(c[1]), "+f"(c[2]), "+f"(c[3])
        : "r"(a[0]), "r"(a[1]), "r"(a[2]), "r"(a[3]), "r"(b[0]), "r"(b[1]));
}

// ---------------- small kernels ----------------
__global__ void scan_kernel(const int* __restrict__ sizes) {
    __shared__ int s[NUM_E];
    int t = threadIdx.x;
    s[t] = sizes[t];
    __syncthreads();
    if (t == 0) {
        int acc = 0;
        #pragma unroll
        for (int i = 0; i < NUM_E; i++) { int v = s[i]; s[i] = acc; acc += v; }
    }
    __syncthreads();
    g_off[t] = s[t];
}

__device__ __forceinline__ void split4(float4 v, ushort4& hv, ushort4& lv) {
    __nv_bfloat16 h0 = __float2bfloat16(v.x);
    __nv_bfloat16 h1 = __float2bfloat16(v.y);
    __nv_bfloat16 h2 = __float2bfloat16(v.z);
    __nv_bfloat16 h3 = __float2bfloat16(v.w);
    __nv_bfloat16 l0 = __float2bfloat16(v.x - __bfloat162float(h0));
    __nv_bfloat16 l1 = __float2bfloat16(v.y - __bfloat162float(h1));
    __nv_bfloat16 l2 = __float2bfloat16(v.z - __bfloat162float(h2));
    __nv_bfloat16 l3 = __float2bfloat16(v.w - __bfloat162float(h3));
    hv = make_ushort4(__bfloat16_as_ushort(h0), __bfloat16_as_ushort(h1),
                      __bfloat16_as_ushort(h2), __bfloat16_as_ushort(h3));
    lv = make_ushort4(__bfloat16_as_ushort(l0), __bfloat16_as_ushort(l1),
                      __bfloat16_as_ushort(l2), __bfloat16_as_ushort(l3));
}

__global__ void convert_a(const float* __restrict__ x) {
    size_t i = (size_t)blockIdx.x * blockDim.x + threadIdx.x;
    size_t stride = (size_t)gridDim.x * blockDim.x;
    const size_t total = (size_t)NTOK * DIM / 4;
    for (; i < total; i += stride) {
        ushort4 hv, lv;
        split4(((const float4*)x)[i], hv, lv);
        ((ushort4*)g_a_hi)[i] = hv;
        ((ushort4*)g_a_lo)[i] = lv;
    }
}

__global__ void convert_w(const float* __restrict__ w) {
    size_t i = (size_t)blockIdx.x * blockDim.x + threadIdx.x;
    size_t stride = (size_t)gridDim.x * blockDim.x;
    const size_t total = (size_t)NUM_E * DIM * DIM / 4;
    for (; i < total; i += stride) {
        ushort4 hv, lv;
        split4(((const float4*)w)[i], hv, lv);
        ((ushort4*)g_w_hi)[i] = hv;
        ((ushort4*)g_w_lo)[i] = lv;
    }
}

// ---------------- grouped GEMM ----------------
__device__ __forceinline__ void load_stage(uint32_t smem_base, int stage, int c,
                                           long tok_base, int e, int col0, int tid) {
    const int kk = c * BK;
    const uint32_t base = smem_base + stage * STAGE_BYTES;
    const uint32_t sAh = base;
    const uint32_t sAl = base + A_TILE_BYTES;
    const uint32_t sBh = base + 2 * A_TILE_BYTES;
    const uint32_t sBl = sBh + B_TILE_BYTES;
    // A: 128 rows x 64B data (4 x 16B chunks), stride 80B
    #pragma unroll
    for (int i = tid; i < 512; i += 256) {
        int r = i >> 2, ch = i & 3;
        long tok = tok_base + r;
        bool v = tok < (long)NTOK;
        size_t g = v ? ((size_t)tok * DIM + kk + ch * 8) : 0;
        uint32_t d = (uint32_t)(r * A_STRIDE + ch * 16);
        cp16(sAh + d, g_a_hi + g, v);
        cp16(sAl + d, g_a_lo + g, v);
    }
    // B: 32 k-rows x 256B data (16 x 16B chunks), stride 272B
    #pragma unroll
    for (int i = tid; i < 512; i += 256) {
        int r = i >> 4, ch = i & 15;
        size_t g = (size_t)e * DIM * DIM + (size_t)(kk + r) * DIM + col0 + ch * 8;
        uint32_t d = (uint32_t)(r * B_STRIDE + ch * 16);
        cp16(sBh + d, g_w_hi + g, true);
        cp16(sBl + d, g_w_lo + g, true);
    }
    asm volatile("cp.async.commit_group;" ::: "memory");
}

__global__ __launch_bounds__(256, 2)
void grouped_gemm(const int* __restrict__ sizes, float* __restrict__ out) {
    extern __shared__ char smem[];
    const int e = blockIdx.z;
    const int size = sizes[e];
    const int row0 = blockIdx.x * BM;
    if (row0 >= size) return;
    const int col0 = blockIdx.y * BN;
    const long tok_base = (long)g_off[e] + row0;

    const uint32_t smem_base = smem_u32(smem);
    const int tid = threadIdx.x;
    const int wid = tid >> 5;
    const int lane = tid & 31;
    const int wm = wid & 3;       // 4 warps along M: 32 rows each
    const int wn = wid >> 2;      // 2 warps along N: 64 cols each
    const int quad = lane >> 3;
    const int lr = lane & 7;

    float acc[2][8][4];
    #pragma unroll
    for (int mt = 0; mt < 2; mt++)
        #pragma unroll
        for (int nt = 0; nt < 8; nt++)
            #pragma unroll
            for (int q = 0; q < 4; q++) acc[mt][nt][q] = 0.f;

    // prologue: depth-2 prefetch (stages 0, 1)
    load_stage(smem_base, 0, 0, tok_base, e, col0, tid);
    load_stage(smem_base, 1, 1, tok_base, e, col0, tid);

    for (int c = 0; c < NCHUNK; c++) {
        // chunk c's group done (own view); <=1 group may stay pending
        if (c == NCHUNK - 1) asm volatile("cp.async.wait_group 0;" ::: "memory");
        else                 asm volatile("cp.async.wait_group 1;" ::: "memory");
        // single barrier: makes chunk c visible to all warps AND guarantees all
        // warps finished reading stage (c+2)%3 (used by chunk c-1) before overwrite
        __syncthreads();
        if (c + 2 < NCHUNK)
            load_stage(smem_base, (c + 2) % NSTAGE, c + 2, tok_base, e, col0, tid);

        const uint32_t base = smem_base + (c % NSTAGE) * STAGE_BYTES;
        const uint32_t sAh = base;
        const uint32_t sAl = base + A_TILE_BYTES;
        const uint32_t sBh = base + 2 * A_TILE_BYTES;
        const uint32_t sBl = sBh + B_TILE_BYTES;

        #pragma unroll
        for (int s = 0; s < 2; s++) {
            uint32_t aHi[2][4], aLo[2][4];
            // A fragments: 16x16 (m x k) per ldmatrix.x4
            #pragma unroll
            for (int mt = 0; mt < 2; mt++) {
                int row = wm * 32 + mt * 16 + (quad & 1) * 8 + lr;
                int kb = s * 32 + (quad >> 1) * 16;
                uint32_t off = (uint32_t)(row * A_STRIDE + kb);
                ldsm_x4(aHi[mt], sAh + off);
                ldsm_x4(aLo[mt], sAl + off);
            }
            // B fragments in two nt-halves to cap register pressure
            #pragma unroll
            for (int h = 0; h < 2; h++) {
                uint32_t bHi[4][2], bLo[4][2];
                #pragma unroll
                for (int j = 0; j < 2; j++) {
                    int nt2 = h * 2 + j;   // 16-col block index
                    int krow = s * 16 + (quad & 1) * 8 + lr;
                    int nb = (wn * 64 + nt2 * 16 + (quad >> 1) * 8) * 2;
                    uint32_t off = (uint32_t)(krow * B_STRIDE + nb);
                    uint32_t rh[4], rl[4];
                    ldsm_x4_t(rh, sBh + off);
                    ldsm_x4_t(rl, sBl + off);
                    bHi[2 * j][0] = rh[0]; bHi[2 * j][1] = rh[1];
                    bHi[2 * j + 1][0] = rh[2]; bHi[2 * j + 1][1] = rh[3];
                    bLo[2 * j][0] = rl[0]; bLo[2 * j][1] = rl[1];
                    bLo[2 * j + 1][0] = rl[2]; bLo[2 * j + 1][1] = rl[3];
                }
                #pragma unroll
                for (int mt = 0; mt < 2; mt++)
                    #pragma unroll
                    for (int j = 0; j < 4; j++) {
                        int nt = h * 4 + j;
                        mma16816(acc[mt][nt], aHi[mt], bHi[j]);
                        mma16816(acc[mt][nt], aLo[mt], bHi[j]);
                        mma16816(acc[mt][nt], aHi[mt], bLo[j]);
                    }
            }
        }
    }

    // ---- epilogue ----
    const int g = lane >> 2;
    const int q = lane & 3;
    #pragma unroll
    for (int mt = 0; mt < 2; mt++) {
        int r_lo = wm * 32 + mt * 16 + g;       // tile-local rows
        int r_hi = r_lo + 8;
        bool v_lo = (row0 + r_lo) < size;
        bool v_hi = (row0 + r_hi) < size;
        float* p_lo = out + (size_t)(tok_base + r_lo) * DIM + col0;
        float* p_hi = out + (size_t)(tok_base + r_hi) * DIM + col0;
        #pragma unroll
        for (int nt = 0; nt < 8; nt++) {
            int cidx = wn * 64 + nt * 8 + q * 2;
            if (v_lo) *(float2*)(p_lo + cidx) = make_float2(acc[mt][nt][0], acc[mt][nt][1]);
            if (v_hi) *(float2*)(p_hi + cidx) = make_float2(acc[mt][nt][2], acc[mt][nt][3]);
        }
    }
}

// ---------------- launch ----------------
extern "C" void kernel_launch(void* const* d_in, const int* in_sizes, int n_in,
                              void* d_out, int out_size) {
    const float* inputs = (const float*)d_in[0];
    const int*   sizes  = (const int*)  d_in[1];
    const float* weight = (const float*)d_in[2];
    float*       out    = (float*)d_out;

    cudaFuncSetAttribute(grouped_gemm, cudaFuncAttributeMaxDynamicSharedMemorySize, SMEM_TOTAL);

    scan_kernel<<<1, NUM_E>>>(sizes);
    convert_a<<<2048, 256>>>(inputs);
    convert_w<<<2048, 256>>>(weight);
    grouped_gemm<<<dim3(CAP / BM, DIM / BN, NUM_E), 256, SMEM_TOTAL>>>(sizes, out);
}

// round 9
// speedup vs baseline: 3.1069x; 1.2638x over previous
#include <cuda_runtime.h>
#include <cstdint>

#define NUM_E 64
#define DIM 512
#define NTOK 131072
#define CAP 3072

#define BM 128
#define BN 128
#define BK 32
#define NCHUNK 16            // 512 / 32
#define NSTAGE 3

#define A_STRIDE 144         // bytes per A smem row: 32 fp32 = 128B data + 16 pad
#define B_STRIDE 544         // bytes per B smem row: 128 fp32 = 512B data + 32 pad
#define A_TILE_BYTES (BM * A_STRIDE)          // 18432
#define B_TILE_BYTES (BK * B_STRIDE)          // 17408
#define STAGE_BYTES (A_TILE_BYTES + B_TILE_BYTES)   // 35840
#define SMEM_TOTAL (NSTAGE * STAGE_BYTES)     // 107520; x2 CTAs = 215040 <= 227KB

__device__ int g_off[NUM_E];

// ---------------- helpers ----------------
__device__ __forceinline__ uint32_t smem_u32(const void* p) {
    uint32_t a;
    asm("{ .reg .u64 t; cvta.to.shared.u64 t, %1; cvt.u32.u64 %0, t; }" : "=r"(a) : "l"(p));
    return a;
}

__device__ __forceinline__ void cp16(uint32_t dst, const void* src, bool pred) {
    int sz = pred ? 16 : 0;
    asm volatile("cp.async.cg.shared.global [%0], [%1], 16, %2;"
        :: "r"(dst), "l"(src), "r"(sz) : "memory");
}

__device__ __forceinline__ uint32_t lds_tf32(uint32_t addr) {
    float f;
    asm volatile("ld.shared.f32 %0, [%1];" : "=f"(f) : "r"(addr));
    uint32_t r;
    asm volatile("cvt.rna.tf32.f32 %0, %1;" : "=r"(r) : "f"(f));
    return r;
}

// m16n8k8 tf32: A 4 regs, B 2 regs, C 4 fp32
__device__ __forceinline__ void mma_tf32(float* c, const uint32_t* a, const uint32_t* b) {
    asm volatile(
        "mma.sync.aligned.m16n8k8.row.col.f32.tf32.tf32.f32 "
        "{%0,%1,%2,%3}, {%4,%5,%6,%7}, {%8,%9}, {%0,%1,%2,%3};"
        : "+f"(c[0]), "+f"(c[1]), "+f"(c[2]), "+f"(c[3])
        : "r"(a[0]), "r"(a[1]), "r"(a[2]), "r"(a[3]), "r"(b[0]), "r"(b[1]));
}

// ---------------- small kernels ----------------
__global__ void scan_kernel(const int* __restrict__ sizes) {
    __shared__ int s[NUM_E];
    int t = threadIdx.x;
    s[t] = sizes[t];
    __syncthreads();
    if (t == 0) {
        int acc = 0;
        #pragma unroll
        for (int i = 0; i < NUM_E; i++) { int v = s[i]; s[i] = acc; acc += v; }
    }
    __syncthreads();
    g_off[t] = s[t];
}

// ---------------- grouped GEMM ----------------
__device__ __forceinline__ void load_stage(uint32_t smem_base, int stage, int c,
                                           long tok_base, int e, int col0, int tid,
                                           const float* __restrict__ inputs,
                                           const float* __restrict__ weight) {
    const int kk = c * BK;
    const uint32_t sA = smem_base + stage * STAGE_BYTES;
    const uint32_t sB = sA + A_TILE_BYTES;
    // A: 128 rows x 128B data (8 x 16B chunks), stride 144B
    #pragma unroll
    for (int i = tid; i < 1024; i += 256) {
        int r = i >> 3, ch = i & 7;
        long tok = tok_base + r;
        bool v = tok < (long)NTOK;
        const float* g = inputs + (v ? ((size_t)tok * DIM + kk + ch * 4) : 0);
        cp16(sA + (uint32_t)(r * A_STRIDE + ch * 16), g, v);
    }
    // B: 32 k-rows x 512B data (32 x 16B chunks), stride 544B
    #pragma unroll
    for (int i = tid; i < 1024; i += 256) {
        int r = i >> 5, ch = i & 31;
        const float* g = weight + (size_t)e * DIM * DIM + (size_t)(kk + r) * DIM + col0 + ch * 4;
        cp16(sB + (uint32_t)(r * B_STRIDE + ch * 16), g, true);
    }
    asm volatile("cp.async.commit_group;" ::: "memory");
}

__global__ __launch_bounds__(256, 2)
void grouped_gemm(const int* __restrict__ sizes,
                  const float* __restrict__ inputs,
                  const float* __restrict__ weight,
                  float* __restrict__ out) {
    extern __shared__ char smem[];
    const int e = blockIdx.z;
    const int size = sizes[e];
    const int row0 = blockIdx.x * BM;
    if (row0 >= size) return;
    const int col0 = blockIdx.y * BN;
    const long tok_base = (long)g_off[e] + row0;

    const uint32_t smem_base = smem_u32(smem);
    const int tid = threadIdx.x;
    const int wid = tid >> 5;
    const int lane = tid & 31;
    const int wm = wid & 3;       // 4 warps along M: 32 rows each
    const int wn = wid >> 2;      // 2 warps along N: 64 cols each
    const int g = lane >> 2;      // group 0..7
    const int t = lane & 3;       // thread-in-group 0..3

    float acc[2][8][4];
    #pragma unroll
    for (int mt = 0; mt < 2; mt++)
        #pragma unroll
        for (int nt = 0; nt < 8; nt++)
            #pragma unroll
            for (int q = 0; q < 4; q++) acc[mt][nt][q] = 0.f;

    // prologue: depth-2 prefetch
    load_stage(smem_base, 0, 0, tok_base, e, col0, tid, inputs, weight);
    load_stage(smem_base, 1, 1, tok_base, e, col0, tid, inputs, weight);

    for (int c = 0; c < NCHUNK; c++) {
        if (c == NCHUNK - 1) asm volatile("cp.async.wait_group 0;" ::: "memory");
        else                 asm volatile("cp.async.wait_group 1;" ::: "memory");
        // single barrier: publishes chunk c AND protects stage (c+2)%3 (read in c-1)
        __syncthreads();
        if (c + 2 < NCHUNK)
            load_stage(smem_base, (c + 2) % NSTAGE, c + 2, tok_base, e, col0, tid, inputs, weight);

        const uint32_t sA = smem_base + (c % NSTAGE) * STAGE_BYTES;
        const uint32_t sB = sA + A_TILE_BYTES;

        #pragma unroll
        for (int ks = 0; ks < 4; ks++) {
            // A fragments: [16x8] per mt; a0=[g][t] a1=[g+8][t] a2=[g][t+4] a3=[g+8][t+4]
            uint32_t a[2][4];
            #pragma unroll
            for (int mt = 0; mt < 2; mt++) {
                uint32_t base = sA + (uint32_t)((wm * 32 + mt * 16 + g) * A_STRIDE + (ks * 8 + t) * 4);
                a[mt][0] = lds_tf32(base);
                a[mt][1] = lds_tf32(base + 8 * A_STRIDE);
                a[mt][2] = lds_tf32(base + 16);
                a[mt][3] = lds_tf32(base + 8 * A_STRIDE + 16);
            }
            // B fragments per nt: [8x8] b0=[t][g] b1=[t+4][g]; then MMA
            #pragma unroll
            for (int nt = 0; nt < 8; nt++) {
                uint32_t baseB = sB + (uint32_t)((ks * 8 + t) * B_STRIDE + (wn * 64 + nt * 8 + g) * 4);
                uint32_t b[2];
                b[0] = lds_tf32(baseB);
                b[1] = lds_tf32(baseB + 4 * B_STRIDE);
                mma_tf32(acc[0][nt], a[0], b);
                mma_tf32(acc[1][nt], a[1], b);
            }
        }
    }

    // ---- epilogue: c0=[g][2t] c1=[g][2t+1] c2=[g+8][2t] c3=[g+8][2t+1]
    #pragma unroll
    for (int mt = 0; mt < 2; mt++) {
        int r_lo = wm * 32 + mt * 16 + g;
        int r_hi = r_lo + 8;
        bool v_lo = (row0 + r_lo) < size;
        bool v_hi = (row0 + r_hi) < size;
        float* p_lo = out + (size_t)(tok_base + r_lo) * DIM + col0;
        float* p_hi = out + (size_t)(tok_base + r_hi) * DIM + col0;
        #pragma unroll
        for (int nt = 0; nt < 8; nt++) {
            int cidx = wn * 64 + nt * 8 + t * 2;
            if (v_lo) *(float2*)(p_lo + cidx) = make_float2(acc[mt][nt][0], acc[mt][nt][1]);
            if (v_hi) *(float2*)(p_hi + cidx) = make_float2(acc[mt][nt][2], acc[mt][nt][3]);
        }
    }
}

// ---------------- launch ----------------
extern "C" void kernel_launch(void* const* d_in, const int* in_sizes, int n_in,
                              void* d_out, int out_size) {
    const float* inputs = (const float*)d_in[0];
    const int*   sizes  = (const int*)  d_in[1];
    const float* weight = (const float*)d_in[2];
    float*       out    = (float*)d_out;

    cudaFuncSetAttribute(grouped_gemm, cudaFuncAttributeMaxDynamicSharedMemorySize, SMEM_TOTAL);

    scan_kernel<<<1, NUM_E>>>(sizes);
    grouped_gemm<<<dim3(CAP / BM, DIM / BN, NUM_E), 256, SMEM_TOTAL>>>(sizes, inputs, weight, out);
}

// round 10
// speedup vs baseline: 3.3822x; 1.0886x over previous
#include <cuda_runtime.h>
#include <cstdint>

#define NUM_E 64
#define DIM 512
#define NTOK 131072
#define CAP 3072

#define BM 128
#define BN 128
#define BK 32
#define NCHUNK 16            // 512 / 32
#define NSTAGE 3

#define ROW_STRIDE 144       // bytes per smem row: 32 fp32 = 128B data + 16 pad
#define A_TILE_BYTES (BM * ROW_STRIDE)        // 18432
#define B_TILE_BYTES (BN * ROW_STRIDE)        // 18432 (n-major: 128 n-rows x 32 k)
#define STAGE_BYTES (A_TILE_BYTES + B_TILE_BYTES)   // 36864
#define SMEM_TOTAL (NSTAGE * STAGE_BYTES)     // 110592; x2 CTAs = 221184 <= 228KB

__device__ int g_off[NUM_E];
__device__ float g_wt[(size_t)NUM_E * DIM * DIM];   // W transposed [e][n][k], tf32-rounded

// ---------------- helpers ----------------
__device__ __forceinline__ uint32_t smem_u32(const void* p) {
    uint32_t a;
    asm("{ .reg .u64 t; cvta.to.shared.u64 t, %1; cvt.u32.u64 %0, t; }" : "=r"(a) : "l"(p));
    return a;
}

__device__ __forceinline__ void cp16(uint32_t dst, const void* src, bool pred) {
    int sz = pred ? 16 : 0;
    asm volatile("cp.async.cg.shared.global [%0], [%1], 16, %2;"
        :: "r"(dst), "l"(src), "r"(sz) : "memory");
}

__device__ __forceinline__ void ldsm_x4(uint32_t* r, uint32_t addr) {
    asm volatile("ldmatrix.sync.aligned.m8n8.x4.shared.b16 {%0,%1,%2,%3}, [%4];"
        : "=r"(r[0]), "=r"(r[1]), "=r"(r[2]), "=r"(r[3]) : "r"(addr));
}

__device__ __forceinline__ uint32_t cvt_tf32(uint32_t x) {
    uint32_t r;
    asm volatile("cvt.rna.tf32.f32 %0, %1;" : "=r"(r) : "f"(__uint_as_float(x)));
    return r;
}

// m16n8k8 tf32: A 4 regs, B 2 regs, C 4 fp32
__device__ __forceinline__ void mma_tf32(float* c, const uint32_t* a,
                                         uint32_t b0, uint32_t b1) {
    asm volatile(
        "mma.sync.aligned.m16n8k8.row.col.f32.tf32.tf32.f32 "
        "{%0,%1,%2,%3}, {%4,%5,%6,%7}, {%8,%9}, {%0,%1,%2,%3};"
        : "+f"(c[0]), "+f"(c[1]), "+f"(c[2]), "+f"(c[3])
        : "r"(a[0]), "r"(a[1]), "r"(a[2]), "r"(a[3]), "r"(b0), "r"(b1));
}

// ---------------- small kernels ----------------
__global__ void scan_kernel(const int* __restrict__ sizes) {
    __shared__ int s[NUM_E];
    int t = threadIdx.x;
    s[t] = sizes[t];
    __syncthreads();
    if (t == 0) {
        int acc = 0;
        #pragma unroll
        for (int i = 0; i < NUM_E; i++) { int v = s[i]; s[i] = acc; acc += v; }
    }
    __syncthreads();
    g_off[t] = s[t];
}

// W[e][k][n] fp32 -> Wt[e][n][k] tf32-rounded fp32
__global__ void convert_w(const float* __restrict__ w) {
    __shared__ float t[32][33];
    const int e = blockIdx.z;
    const int k0 = blockIdx.x * 32, n0 = blockIdx.y * 32;
    const float* W = w + (size_t)e * DIM * DIM;
    #pragma unroll
    for (int p = 0; p < 32; p += 8)
        t[threadIdx.y + p][threadIdx.x] = W[(size_t)(k0 + threadIdx.y + p) * DIM + n0 + threadIdx.x];
    __syncthreads();
    #pragma unroll
    for (int p = 0; p < 32; p += 8) {
        int n = n0 + threadIdx.y + p;
        int k = k0 + threadIdx.x;
        float v = t[threadIdx.x][threadIdx.y + p];
        uint32_t r;
        asm volatile("cvt.rna.tf32.f32 %0, %1;" : "=r"(r) : "f"(v));
        g_wt[(size_t)e * DIM * DIM + (size_t)n * DIM + k] = __uint_as_float(r);
    }
}

// ---------------- grouped GEMM ----------------
__device__ __forceinline__ void load_stage(uint32_t smem_base, int stage, int c,
                                           long tok_base, int e, int col0, int tid,
                                           const float* __restrict__ inputs) {
    const int kk = c * BK;
    const uint32_t sA = smem_base + stage * STAGE_BYTES;
    const uint32_t sB = sA + A_TILE_BYTES;
    // A: 128 m-rows x 128B data (8 x 16B chunks), stride 144B
    #pragma unroll
    for (int i = tid; i < 1024; i += 256) {
        int r = i >> 3, ch = i & 7;
        long tok = tok_base + r;
        bool v = tok < (long)NTOK;
        const float* g = inputs + (v ? ((size_t)tok * DIM + kk + ch * 4) : 0);
        cp16(sA + (uint32_t)(r * ROW_STRIDE + ch * 16), g, v);
    }
    // B: 128 n-rows x 128B data (8 x 16B chunks of k), stride 144B, from Wt[e][n][k]
    #pragma unroll
    for (int i = tid; i < 1024; i += 256) {
        int r = i >> 3, ch = i & 7;
        const float* g = g_wt + (size_t)e * DIM * DIM + (size_t)(col0 + r) * DIM + kk + ch * 4;
        cp16(sB + (uint32_t)(r * ROW_STRIDE + ch * 16), g, true);
    }
    asm volatile("cp.async.commit_group;" ::: "memory");
}

__global__ __launch_bounds__(256, 2)
void grouped_gemm(const int* __restrict__ sizes,
                  const float* __restrict__ inputs,
                  float* __restrict__ out) {
    extern __shared__ char smem[];
    const int e = blockIdx.z;
    const int size = sizes[e];
    const int row0 = blockIdx.x * BM;
    if (row0 >= size) return;
    const int col0 = blockIdx.y * BN;
    const long tok_base = (long)g_off[e] + row0;

    const uint32_t smem_base = smem_u32(smem);
    const int tid = threadIdx.x;
    const int wid = tid >> 5;
    const int lane = tid & 31;
    const int wm = wid & 3;       // 4 warps along M: 32 rows each
    const int wn = wid >> 2;      // 2 warps along N: 64 cols each
    const int g = lane >> 2;      // group 0..7
    const int t = lane & 3;       // thread-in-group 0..3

    // ldmatrix lane-address components
    const int a_row  = lane & 15;            // row within 16-row fragment
    const int a_koff = (lane >> 4) * 4;      // fp32 k-offset 0 or 4
    const int b_m    = lane >> 3;            // matrix index 0..3
    const int b_row  = ((b_m >> 1) * 8) + (lane & 7);   // n-row within 16-row pair
    const int b_koff = (b_m & 1) * 4;        // fp32 k-offset 0 or 4

    float acc[2][8][4];
    #pragma unroll
    for (int mt = 0; mt < 2; mt++)
        #pragma unroll
        for (int nt = 0; nt < 8; nt++)
            #pragma unroll
            for (int q = 0; q < 4; q++) acc[mt][nt][q] = 0.f;

    // prologue: depth-2 prefetch
    load_stage(smem_base, 0, 0, tok_base, e, col0, tid, inputs);
    load_stage(smem_base, 1, 1, tok_base, e, col0, tid, inputs);

    for (int c = 0; c < NCHUNK; c++) {
        if (c == NCHUNK - 1) asm volatile("cp.async.wait_group 0;" ::: "memory");
        else                 asm volatile("cp.async.wait_group 1;" ::: "memory");
        // single barrier: publishes chunk c AND protects stage (c+2)%3 (read in c-1)
        __syncthreads();
        if (c + 2 < NCHUNK)
            load_stage(smem_base, (c + 2) % NSTAGE, c + 2, tok_base, e, col0, tid, inputs);

        const uint32_t sA = smem_base + (c % NSTAGE) * STAGE_BYTES;
        const uint32_t sB = sA + A_TILE_BYTES;

        #pragma unroll
        for (int ks = 0; ks < 4; ks++) {
            // A fragments: one ldmatrix.x4 per mt -> a0=[g][t] a1=[g+8][t] a2=[g][t+4] a3=[g+8][t+4]
            uint32_t a[2][4];
            #pragma unroll
            for (int mt = 0; mt < 2; mt++) {
                uint32_t addr = sA + (uint32_t)((wm * 32 + mt * 16 + a_row) * ROW_STRIDE
                                                + (ks * 8 + a_koff) * 4);
                ldsm_x4(a[mt], addr);
                a[mt][0] = cvt_tf32(a[mt][0]);
                a[mt][1] = cvt_tf32(a[mt][1]);
                a[mt][2] = cvt_tf32(a[mt][2]);
                a[mt][3] = cvt_tf32(a[mt][3]);
            }
            // B: one ldmatrix.x4 per 16-col pair p covers nt=2p (r0,r1) and nt=2p+1 (r2,r3)
            #pragma unroll
            for (int p = 0; p < 4; p++) {
                uint32_t addr = sB + (uint32_t)((wn * 64 + p * 16 + b_row) * ROW_STRIDE
                                                + (ks * 8 + b_koff) * 4);
                uint32_t b[4];
                ldsm_x4(b, addr);       // pre-rounded in convert_w: no cvt needed
                mma_tf32(acc[0][2 * p],     a[0], b[0], b[1]);
                mma_tf32(acc[1][2 * p],     a[1], b[0], b[1]);
                mma_tf32(acc[0][2 * p + 1], a[0], b[2], b[3]);
                mma_tf32(acc[1][2 * p + 1], a[1], b[2], b[3]);
            }
        }
    }

    // ---- epilogue: c0=[g][2t] c1=[g][2t+1] c2=[g+8][2t] c3=[g+8][2t+1]
    #pragma unroll
    for (int mt = 0; mt < 2; mt++) {
        int r_lo = wm * 32 + mt * 16 + g;
        int r_hi = r_lo + 8;
        bool v_lo = (row0 + r_lo) < size;
        bool v_hi = (row0 + r_hi) < size;
        float* p_lo = out + (size_t)(tok_base + r_lo) * DIM + col0;
        float* p_hi = out + (size_t)(tok_base + r_hi) * DIM + col0;
        #pragma unroll
        for (int nt = 0; nt < 8; nt++) {
            int cidx = wn * 64 + nt * 8 + t * 2;
            if (v_lo) *(float2*)(p_lo + cidx) = make_float2(acc[mt][nt][0], acc[mt][nt][1]);
            if (v_hi) *(float2*)(p_hi + cidx) = make_float2(acc[mt][nt][2], acc[mt][nt][3]);
        }
    }
}

// ---------------- launch ----------------
extern "C" void kernel_launch(void* const* d_in, const int* in_sizes, int n_in,
                              void* d_out, int out_size) {
    const float* inputs = (const float*)d_in[0];
    const int*   sizes  = (const int*)  d_in[1];
    const float* weight = (const float*)d_in[2];
    float*       out    = (float*)d_out;

    cudaFuncSetAttribute(grouped_gemm, cudaFuncAttributeMaxDynamicSharedMemorySize, SMEM_TOTAL);

    scan_kernel<<<1, NUM_E>>>(sizes);
    convert_w<<<dim3(16, 16, 64), dim3(32, 8)>>>(weight);
    grouped_gemm<<<dim3(CAP / BM, DIM / BN, NUM_E), 256, SMEM_TOTAL>>>(sizes, inputs, out);
}

// round 11
// speedup vs baseline: 3.4990x; 1.0345x over previous
#include <cuda_runtime.h>
#include <cstdint>

#define NUM_E 64
#define DIM 512
#define NTOK 131072
#define CAP 3072

#define BM 128
#define BN 128
#define BK 32
#define NCHUNK 16            // 512 / 32
#define NSTAGE 3

#define ROW_STRIDE 144       // bytes per smem row: 32 fp32 = 128B data + 16 pad
#define A_TILE_BYTES (BM * ROW_STRIDE)        // 18432
#define B_TILE_BYTES (BN * ROW_STRIDE)        // 18432 (n-major: 128 n-rows x 32 k)
#define STAGE_BYTES (A_TILE_BYTES + B_TILE_BYTES)   // 36864
#define SMEM_TOTAL (NSTAGE * STAGE_BYTES)     // 110592; x2 CTAs = 221184 <= 228KB

__device__ int g_off[NUM_E];
__device__ float g_wt[(size_t)NUM_E * DIM * DIM];   // W transposed [e][n][k], tf32-rounded

// ---------------- helpers ----------------
__device__ __forceinline__ uint32_t smem_u32(const void* p) {
    uint32_t a;
    asm("{ .reg .u64 t; cvta.to.shared.u64 t, %1; cvt.u32.u64 %0, t; }" : "=r"(a) : "l"(p));
    return a;
}

__device__ __forceinline__ void cp16(uint32_t dst, const void* src, bool pred) {
    int sz = pred ? 16 : 0;
    asm volatile("cp.async.cg.shared.global [%0], [%1], 16, %2;"
        :: "r"(dst), "l"(src), "r"(sz) : "memory");
}

__device__ __forceinline__ void ldsm_x4(uint32_t* r, uint32_t addr) {
    asm volatile("ldmatrix.sync.aligned.m8n8.x4.shared.b16 {%0,%1,%2,%3}, [%4];"
        : "=r"(r[0]), "=r"(r[1]), "=r"(r[2]), "=r"(r[3]) : "r"(addr));
}

// m16n8k8 tf32: A 4 regs, B 2 regs, C 4 fp32
__device__ __forceinline__ void mma_tf32(float* c, const uint32_t* a,
                                         uint32_t b0, uint32_t b1) {
    asm volatile(
        "mma.sync.aligned.m16n8k8.row.col.f32.tf32.tf32.f32 "
        "{%0,%1,%2,%3}, {%4,%5,%6,%7}, {%8,%9}, {%0,%1,%2,%3};"
        : "+f"(c[0]), "+f"(c[1]), "+f"(c[2]), "+f"(c[3])
        : "r"(a[0]), "r"(a[1]), "r"(a[2]), "r"(a[3]), "r"(b0), "r"(b1));
}

// ---------------- small kernels ----------------
__global__ void scan_kernel(const int* __restrict__ sizes) {
    __shared__ int s[NUM_E];
    int t = threadIdx.x;
    s[t] = sizes[t];
    __syncthreads();
    if (t == 0) {
        int acc = 0;
        #pragma unroll
        for (int i = 0; i < NUM_E; i++) { int v = s[i]; s[i] = acc; acc += v; }
    }
    __syncthreads();
    g_off[t] = s[t];
}

// W[e][k][n] fp32 -> Wt[e][n][k] tf32-rounded fp32
__global__ void convert_w(const float* __restrict__ w) {
    __shared__ float t[32][33];
    const int e = blockIdx.z;
    const int k0 = blockIdx.x * 32, n0 = blockIdx.y * 32;
    const float* W = w + (size_t)e * DIM * DIM;
    #pragma unroll
    for (int p = 0; p < 32; p += 8)
        t[threadIdx.y + p][threadIdx.x] = W[(size_t)(k0 + threadIdx.y + p) * DIM + n0 + threadIdx.x];
    __syncthreads();
    #pragma unroll
    for (int p = 0; p < 32; p += 8) {
        int n = n0 + threadIdx.y + p;
        int k = k0 + threadIdx.x;
        float v = t[threadIdx.x][threadIdx.y + p];
        uint32_t r;
        asm volatile("cvt.rna.tf32.f32 %0, %1;" : "=r"(r) : "f"(v));
        g_wt[(size_t)e * DIM * DIM + (size_t)n * DIM + k] = __uint_as_float(r);
    }
}

// ---------------- grouped GEMM ----------------
__device__ __forceinline__ void load_stage(uint32_t smem_base, int stage, int c,
                                           long tok_base, int e, int col0, int tid,
                                           const float* __restrict__ inputs) {
    const int kk = c * BK;
    const uint32_t sA = smem_base + stage * STAGE_BYTES;
    const uint32_t sB = sA + A_TILE_BYTES;
    // A: 128 m-rows x 128B data (8 x 16B chunks), stride 144B
    #pragma unroll
    for (int i = tid; i < 1024; i += 256) {
        int r = i >> 3, ch = i & 7;
        long tok = tok_base + r;
        bool v = tok < (long)NTOK;
        const float* g = inputs + (v ? ((size_t)tok * DIM + kk + ch * 4) : 0);
        cp16(sA + (uint32_t)(r * ROW_STRIDE + ch * 16), g, v);
    }
    // B: 128 n-rows x 128B data (8 x 16B chunks of k), stride 144B, from Wt[e][n][k]
    #pragma unroll
    for (int i = tid; i < 1024; i += 256) {
        int r = i >> 3, ch = i & 7;
        const float* g = g_wt + (size_t)e * DIM * DIM + (size_t)(col0 + r) * DIM + kk + ch * 4;
        cp16(sB + (uint32_t)(r * ROW_STRIDE + ch * 16), g, true);
    }
    asm volatile("cp.async.commit_group;" ::: "memory");
}

__global__ __launch_bounds__(256, 2)
void grouped_gemm(const int* __restrict__ sizes,
                  const float* __restrict__ inputs,
                  float* __restrict__ out) {
    extern __shared__ char smem[];
    const int e = blockIdx.z;
    const int size = sizes[e];
    const int row0 = blockIdx.x * BM;
    if (row0 >= size) return;
    const int col0 = blockIdx.y * BN;
    const long tok_base = (long)g_off[e] + row0;

    const uint32_t smem_base = smem_u32(smem);
    const int tid = threadIdx.x;
    const int wid = tid >> 5;
    const int lane = tid & 31;
    const int wm = wid & 3;       // 4 warps along M: 32 rows each
    const int wn = wid >> 2;      // 2 warps along N: 64 cols each
    const int g = lane >> 2;      // group 0..7
    const int t = lane & 3;       // thread-in-group 0..3

    // ldmatrix lane-address components
    const int a_row  = lane & 15;            // row within 16-row fragment
    const int a_koff = (lane >> 4) * 4;      // fp32 k-offset 0 or 4
    const int b_m    = lane >> 3;            // matrix index 0..3
    const int b_row  = ((b_m >> 1) * 8) + (lane & 7);   // n-row within 16-row pair
    const int b_koff = (b_m & 1) * 4;        // fp32 k-offset 0 or 4

    float acc[2][8][4];
    #pragma unroll
    for (int mt = 0; mt < 2; mt++)
        #pragma unroll
        for (int nt = 0; nt < 8; nt++)
            #pragma unroll
            for (int q = 0; q < 4; q++) acc[mt][nt][q] = 0.f;

    // prologue: depth-2 prefetch
    load_stage(smem_base, 0, 0, tok_base, e, col0, tid, inputs);
    load_stage(smem_base, 1, 1, tok_base, e, col0, tid, inputs);

    for (int c = 0; c < NCHUNK; c++) {
        if (c == NCHUNK - 1) asm volatile("cp.async.wait_group 0;" ::: "memory");
        else                 asm volatile("cp.async.wait_group 1;" ::: "memory");
        // single barrier: publishes chunk c AND protects stage (c+2)%3 (read in c-1)
        __syncthreads();
        if (c + 2 < NCHUNK)
            load_stage(smem_base, (c + 2) % NSTAGE, c + 2, tok_base, e, col0, tid, inputs);

        const uint32_t sA = smem_base + (c % NSTAGE) * STAGE_BYTES;
        const uint32_t sB = sA + A_TILE_BYTES;

        #pragma unroll
        for (int ks = 0; ks < 4; ks++) {
            // A fragments: one ldmatrix.x4 per mt; raw fp32 bits — TF32 MMA uses top 19 bits
            uint32_t a[2][4];
            #pragma unroll
            for (int mt = 0; mt < 2; mt++) {
                uint32_t addr = sA + (uint32_t)((wm * 32 + mt * 16 + a_row) * ROW_STRIDE
                                                + (ks * 8 + a_koff) * 4);
                ldsm_x4(a[mt], addr);
            }
            // B: one ldmatrix.x4 per 16-col pair p covers nt=2p (r0,r1) and nt=2p+1 (r2,r3)
            #pragma unroll
            for (int p = 0; p < 4; p++) {
                uint32_t addr = sB + (uint32_t)((wn * 64 + p * 16 + b_row) * ROW_STRIDE
                                                + (ks * 8 + b_koff) * 4);
                uint32_t b[4];
                ldsm_x4(b, addr);       // pre-rounded (rna) in convert_w
                mma_tf32(acc[0][2 * p],     a[0], b[0], b[1]);
                mma_tf32(acc[1][2 * p],     a[1], b[0], b[1]);
                mma_tf32(acc[0][2 * p + 1], a[0], b[2], b[3]);
                mma_tf32(acc[1][2 * p + 1], a[1], b[2], b[3]);
            }
        }
    }

    // ---- epilogue: c0=[g][2t] c1=[g][2t+1] c2=[g+8][2t] c3=[g+8][2t+1]
    #pragma unroll
    for (int mt = 0; mt < 2; mt++) {
        int r_lo = wm * 32 + mt * 16 + g;
        int r_hi = r_lo + 8;
        bool v_lo = (row0 + r_lo) < size;
        bool v_hi = (row0 + r_hi) < size;
        float* p_lo = out + (size_t)(tok_base + r_lo) * DIM + col0;
        float* p_hi = out + (size_t)(tok_base + r_hi) * DIM + col0;
        #pragma unroll
        for (int nt = 0; nt < 8; nt++) {
            int cidx = wn * 64 + nt * 8 + t * 2;
            if (v_lo) *(float2*)(p_lo + cidx) = make_float2(acc[mt][nt][0], acc[mt][nt][1]);
            if (v_hi) *(float2*)(p_hi + cidx) = make_float2(acc[mt][nt][2], acc[mt][nt][3]);
        }
    }
}

// ---------------- launch ----------------
extern "C" void kernel_launch(void* const* d_in, const int* in_sizes, int n_in,
                              void* d_out, int out_size) {
    const float* inputs = (const float*)d_in[0];
    const int*   sizes  = (const int*)  d_in[1];
    const float* weight = (const float*)d_in[2];
    float*       out    = (float*)d_out;

    cudaFuncSetAttribute(grouped_gemm, cudaFuncAttributeMaxDynamicSharedMemorySize, SMEM_TOTAL);

    scan_kernel<<<1, NUM_E>>>(sizes);
    convert_w<<<dim3(16, 16, 64), dim3(32, 8)>>>(weight);
    grouped_gemm<<<dim3(CAP / BM, DIM / BN, NUM_E), 256, SMEM_TOTAL>>>(sizes, inputs, out);
}